// round 12
// baseline (speedup 1.0000x reference)
#include <cuda_runtime.h>
#include <cuda_bf16.h>
#include <math.h>

// ---------------- problem constants ----------------
#define NN  100000
#define HD  128
#define EE  1600000
#define FIN 256
#define KD  5

// ---------------- scratch (static __device__, no allocation) ----------------
__device__ __nv_bfloat16 g_hb16 [(size_t)NN * HD];
__device__ __nv_bfloat16 g_h2b16[(size_t)NN * HD];
__device__ __nv_bfloat16 g_aggb16[(size_t)NN * HD];
__device__ __nv_bfloat16 g_y0b16[(size_t)NN * HD];
__device__ __nv_bfloat16 g_y1b16[(size_t)NN * HD];
// slots 0..5: HD x HD weights [n][k]; slot 6 (at 6*HD*HD): pre_W^T [128n][256k]
__device__ __nv_bfloat16 g_wt[6 * HD * HD + HD * FIN];

__device__ int g_csr_src[EE];
// INVARIANT: g_counts is all-zero at kernel_launch entry (zero-initialized at
// module load; scan3 re-zeroes after its last read on every execution).
__device__ int g_counts[NN];
__device__ int g_incl[NN];
__device__ int g_offs[NN + 1];
__device__ int g_cursor[NN];
__device__ int g_bsum[256];

// folded final-layer vectors: out = sigmoid(h_final . vfeat + y2 . vdist + cc)
__device__ float g_vfeat[HD];
__device__ float g_vdist[HD];
__device__ float g_cc;

// ---------------- edge-index dtype detection (block-local) ----------------
// int64 little-endian with values < 2^31 => every odd 32-bit word of the first
// 32 elements is zero; for int32 those words are random indices (P[all 32
// zero] ~ 1e-160).
__device__ __forceinline__ int detect_flag64(const unsigned* __restrict__ ei) {
    unsigned any = 0;
#pragma unroll
    for (int j = 1; j < 64; j += 2) any |= ei[j];
    return (any == 0) ? 1 : 0;
}

// ---------------- histogram + zero out (counts pre-zeroed by invariant) ----------------
__global__ void histogram_kernel(const int* __restrict__ p32,
                                 float* __restrict__ out, int E, int n) {
    __shared__ int sflag;
    if (threadIdx.x == 0) sflag = detect_flag64((const unsigned*)p32);
    int i = blockIdx.x * blockDim.x + threadIdx.x;
    if (i < n) out[i] = 0.f;
    __syncthreads();
    if (i >= E) return;
    int d = sflag ? p32[2 * ((size_t)E + i)] : p32[E + i];
    atomicAdd(&g_counts[d], 1);
}

__global__ void scan1_kernel(int n) {
    __shared__ int s[1024];
    int i = blockIdx.x * 1024 + threadIdx.x;
    int v = (i < n) ? g_counts[i] : 0;
    s[threadIdx.x] = v;
    __syncthreads();
#pragma unroll
    for (int off = 1; off < 1024; off <<= 1) {
        int t = (threadIdx.x >= off) ? s[threadIdx.x - off] : 0;
        __syncthreads();
        s[threadIdx.x] += t;
        __syncthreads();
    }
    if (i < n) g_incl[i] = s[threadIdx.x];
    if (threadIdx.x == 1023) g_bsum[blockIdx.x] = s[1023];
}

// scan3: per-block base = sum of bsum[0 .. (blockChunk>>2)-1], computed in-block.
// Also re-zeroes g_counts after last read (restores the invariant).
__global__ void scan3_kernel(int n, int E, int nb) {
    __shared__ int s[256];
    int tid = threadIdx.x;
    int myblk = (int)(blockIdx.x >> 2);   // which scan1 block my 256-chunk lies in
    int v = (tid < nb && tid < myblk) ? g_bsum[tid] : 0;
    s[tid] = v;
    __syncthreads();
#pragma unroll
    for (int off = 128; off > 0; off >>= 1) {
        if (tid < off) s[tid] += s[tid + off];
        __syncthreads();
    }
    int base = s[0];
    int i = blockIdx.x * 256 + tid;
    if (i >= n) return;
    int off = base + g_incl[i] - g_counts[i];
    g_offs[i] = off;
    g_cursor[i] = off;
    g_counts[i] = 0;                       // restore invariant for next launch
    if (i == n - 1) g_offs[n] = E;
}

// ---------------- scatter (blocks < SG) + prep (blocks >= SG) ----------------
__global__ void scatter_prep_kernel(
    const int* __restrict__ p32, int E, int SG,
    const float* __restrict__ np_W, const float* __restrict__ np_b,
    const float* __restrict__ d_W3, const float* __restrict__ d_b3,
    const float* __restrict__ fW, const float* __restrict__ fb,
    const float* __restrict__ w0, const float* __restrict__ w1,
    const float* __restrict__ w2, const float* __restrict__ w3,
    const float* __restrict__ w4, const float* __restrict__ w5,
    const float* __restrict__ preW)
{
    if (blockIdx.x < SG) {
        __shared__ int sflag;
        if (threadIdx.x == 0) sflag = detect_flag64((const unsigned*)p32);
        __syncthreads();
        int i = blockIdx.x * 256 + threadIdx.x;
        if (i >= E) return;
        int s, d;
        if (sflag) {
            s = p32[2 * (size_t)i];
            d = p32[2 * ((size_t)E + i)];
        } else {
            s = p32[i];
            d = p32[E + i];
        }
        int pos = atomicAdd(&g_cursor[d], 1);
        g_csr_src[pos] = s;
        return;
    }
    int pb = blockIdx.x - SG;
    if (pb == 0) {
        int j = threadIdx.x;
        if (j < HD) {
            float vf = 0.f, vd = 0.f;
#pragma unroll 8
            for (int k = 0; k < HD; ++k) {
                vf += np_W[j * HD + k] * fW[k];
                vd += d_W3[j * HD + k] * fW[HD + k];
            }
            g_vfeat[j] = vf;
            g_vdist[j] = vd;
            if (j == 0) {
                float c = fb[0];
                for (int k = 0; k < HD; ++k)
                    c += np_b[k] * fW[k] + d_b3[k] * fW[HD + k];
                g_cc = c;
            }
        }
        return;
    }
    int i = (pb - 1) * 256 + threadIdx.x;
    if (i < 6 * HD * HD) {
        int m = i >> 14;
        int r = i & (HD * HD - 1);
        int n = r >> 7;
        int k = r & 127;
        const float* src = (m == 0) ? w0 : (m == 1) ? w1 : (m == 2) ? w2
                         : (m == 3) ? w3 : (m == 4) ? w4 : w5;
        g_wt[i] = __float2bfloat16(src[k * HD + n]);
    } else if (i < 6 * HD * HD + HD * FIN) {
        int j = i - 6 * HD * HD;     // n*256 + k
        int n = j >> 8;
        int k = j & 255;
        g_wt[i] = __float2bfloat16(preW[k * HD + n]);
    }
}

// ---------------- mean aggregation: 16 lanes/node, uint4 bf16 gather ----------------
__global__ void mean_agg_kernel(const __nv_bfloat16* __restrict__ h16,
                                __nv_bfloat16* __restrict__ agg16, int n) {
    int idx = blockIdx.x * blockDim.x + threadIdx.x;
    int node = idx >> 4;
    int lane = idx & 15;
    if (node >= n) return;
    int s = g_offs[node];
    int e = g_offs[node + 1];
    float a0 = 0.f, a1 = 0.f, a2 = 0.f, a3 = 0.f,
          a4 = 0.f, a5 = 0.f, a6 = 0.f, a7 = 0.f;
    int i = s;
    for (; i + 4 <= e; i += 4) {
        int s0 = __ldg(&g_csr_src[i]);
        int s1 = __ldg(&g_csr_src[i + 1]);
        int s2 = __ldg(&g_csr_src[i + 2]);
        int s3 = __ldg(&g_csr_src[i + 3]);
        uint4 u0 = ((const uint4*)(h16 + (size_t)s0 * HD))[lane];
        uint4 u1 = ((const uint4*)(h16 + (size_t)s1 * HD))[lane];
        uint4 u2 = ((const uint4*)(h16 + (size_t)s2 * HD))[lane];
        uint4 u3 = ((const uint4*)(h16 + (size_t)s3 * HD))[lane];
        float2 p;
#define ACC8(u) \
        p = __bfloat1622float2(*(__nv_bfloat162*)&(u).x); a0 += p.x; a1 += p.y; \
        p = __bfloat1622float2(*(__nv_bfloat162*)&(u).y); a2 += p.x; a3 += p.y; \
        p = __bfloat1622float2(*(__nv_bfloat162*)&(u).z); a4 += p.x; a5 += p.y; \
        p = __bfloat1622float2(*(__nv_bfloat162*)&(u).w); a6 += p.x; a7 += p.y;
        ACC8(u0); ACC8(u1); ACC8(u2); ACC8(u3);
    }
    for (; i < e; ++i) {
        int s0 = __ldg(&g_csr_src[i]);
        uint4 u0 = ((const uint4*)(h16 + (size_t)s0 * HD))[lane];
        float2 p;
        ACC8(u0);
    }
#undef ACC8
    float inv = 1.0f / (float)max(e - s, 1);
    uint4 r;
    *(__nv_bfloat162*)&r.x = __float22bfloat162_rn(make_float2(a0 * inv, a1 * inv));
    *(__nv_bfloat162*)&r.y = __float22bfloat162_rn(make_float2(a2 * inv, a3 * inv));
    *(__nv_bfloat162*)&r.z = __float22bfloat162_rn(make_float2(a4 * inv, a5 * inv));
    *(__nv_bfloat162*)&r.w = __float22bfloat162_rn(make_float2(a6 * inv, a7 * inv));
    ((uint4*)(agg16 + (size_t)node * HD))[lane] = r;
}

// ================= common helpers =================
__device__ __forceinline__ unsigned smem_u32p(const void* p) {
    return (unsigned)__cvta_generic_to_shared(p);
}
__device__ __forceinline__ void cp_async16(unsigned dst, const void* src, int pred) {
    asm volatile("cp.async.cg.shared.global [%0], [%1], 16, %2;\n"
                 :: "r"(dst), "l"(src), "r"(pred ? 16 : 0));
}
__device__ __forceinline__ void mma_bf16(float* c, const unsigned* a, const unsigned* b) {
    asm volatile(
        "mma.sync.aligned.m16n8k16.row.col.f32.bf16.bf16.f32 "
        "{%0,%1,%2,%3}, {%4,%5,%6,%7}, {%8,%9}, {%0,%1,%2,%3};"
        : "+f"(c[0]), "+f"(c[1]), "+f"(c[2]), "+f"(c[3])
        : "r"(a[0]), "r"(a[1]), "r"(a[2]), "r"(a[3]), "r"(b[0]), "r"(b[1]));
}

#define BM 128
#define BN 128
#define BK 32

// ---------------- PRE GEMM (blocks < G) + dist0 (blocks >= G) ----------------
#define PSA 36   // fp32 A stride
#define PSB 40   // bf16 B stride
#define PRE_STAGE_BYTES (128 * PSA * 4 + 128 * PSB * 2)   // 28672
#define PRE_SMEM (2 * PRE_STAGE_BYTES)                    // 57344
#define D0_ROWS 32   // rows per dist0 block (256 threads, 2 rows in flight)

__device__ __forceinline__ void pre_load_tile(
    float* As, __nv_bfloat16* Bs,
    const float* __restrict__ A, const __nv_bfloat16* __restrict__ Wt,
    int k0, int row0, int M, int tid)
{
#pragma unroll
    for (int i = 0; i < 4; ++i) {
        int c = tid + i * 256;
        int r = c >> 3;
        int off = (c & 7) * 4;
        int gr = row0 + r;
        cp_async16(smem_u32p(As + r * PSA + off),
                   A + (size_t)gr * FIN + k0 + off, gr < M);
    }
#pragma unroll
    for (int i = 0; i < 2; ++i) {
        int c = tid + i * 256;
        int r = c >> 2;
        int j = c & 3;
        cp_async16(smem_u32p(Bs + r * PSB + j * 8),
                   Wt + (size_t)r * FIN + k0 + j * 8, 1);
    }
    asm volatile("cp.async.commit_group;\n" ::);
}

__global__ void __launch_bounds__(256, 2) pre_gemm_kernel(
    const float* __restrict__ A, const __nv_bfloat16* __restrict__ Wt,
    const float* __restrict__ bias, __nv_bfloat16* __restrict__ C16, int M, int G,
    const float* __restrict__ e, const float* __restrict__ W0,
    const float* __restrict__ b0, __nv_bfloat16* __restrict__ y0)
{
    extern __shared__ char smraw[];

    int tid = threadIdx.x;

    if (blockIdx.x >= G) {
        // ---- dist0: y0 = relu(e[M,5] @ W0[5,128] + b0) ----
        float* ws = (float*)smraw;
        for (int i = tid; i < KD * HD; i += 256) ws[i] = W0[i];
        __syncthreads();
        int c = tid & 127;
        float bv = b0[c];
        int r0 = (blockIdx.x - G) * D0_ROWS + (tid >> 7);
        for (int rr = 0; rr < D0_ROWS; rr += 2) {
            int r = r0 + rr;
            if (r >= M) return;
            float acc = bv;
#pragma unroll
            for (int k = 0; k < KD; ++k)
                acc += e[(size_t)r * KD + k] * ws[k * HD + c];
            y0[(size_t)r * HD + c] = __float2bfloat16(fmaxf(acc, 0.f));
        }
        return;
    }

    float* AsB[2] = { (float*)smraw, (float*)(smraw + PRE_STAGE_BYTES) };
    __nv_bfloat16* BsB[2] = {
        (__nv_bfloat16*)(smraw + 128 * PSA * 4),
        (__nv_bfloat16*)(smraw + PRE_STAGE_BYTES + 128 * PSA * 4) };

    int lane = tid & 31;
    int warp = tid >> 5;
    int wm = (warp >> 2) * 64;
    int wn = (warp & 3) * 32;
    int row0 = blockIdx.x * BM;
    int g = lane >> 2;
    int q = lane & 3;

    float acc[4][4][4];
#pragma unroll
    for (int i = 0; i < 4; ++i)
#pragma unroll
        for (int j = 0; j < 4; ++j)
#pragma unroll
            for (int k = 0; k < 4; ++k) acc[i][j][k] = 0.f;

    int total = FIN / BK;   // 8
    pre_load_tile(AsB[0], BsB[0], A, Wt, 0, row0, M, tid);

    for (int t = 0; t < total; ++t) {
        if (t + 1 < total) {
            pre_load_tile(AsB[(t + 1) & 1], BsB[(t + 1) & 1], A, Wt,
                          (t + 1) * BK, row0, M, tid);
            asm volatile("cp.async.wait_group 1;\n" ::);
        } else {
            asm volatile("cp.async.wait_group 0;\n" ::);
        }
        __syncthreads();

        const float* As = AsB[t & 1];
        const __nv_bfloat16* Bs = BsB[t & 1];
#pragma unroll
        for (int kk = 0; kk < BK; kk += 16) {
            int kq = kk + 2 * q;
            unsigned a[4][4], b[4][2];
#pragma unroll
            for (int fm = 0; fm < 4; ++fm) {
                int m = wm + fm * 16 + g;
                float2 f;
                f = *(const float2*)&As[m * PSA + kq];
                *(__nv_bfloat162*)&a[fm][0] = __float22bfloat162_rn(f);
                f = *(const float2*)&As[(m + 8) * PSA + kq];
                *(__nv_bfloat162*)&a[fm][1] = __float22bfloat162_rn(f);
                f = *(const float2*)&As[m * PSA + kq + 8];
                *(__nv_bfloat162*)&a[fm][2] = __float22bfloat162_rn(f);
                f = *(const float2*)&As[(m + 8) * PSA + kq + 8];
                *(__nv_bfloat162*)&a[fm][3] = __float22bfloat162_rn(f);
            }
#pragma unroll
            for (int fn = 0; fn < 4; ++fn) {
                int n = wn + fn * 8 + g;
                b[fn][0] = *(const unsigned*)&Bs[n * PSB + kq];
                b[fn][1] = *(const unsigned*)&Bs[n * PSB + kq + 8];
            }
#pragma unroll
            for (int fm = 0; fm < 4; ++fm)
#pragma unroll
                for (int fn = 0; fn < 4; ++fn)
                    mma_bf16(acc[fm][fn], a[fm], b[fn]);
        }
        __syncthreads();
    }

#pragma unroll
    for (int fm = 0; fm < 4; ++fm) {
#pragma unroll
        for (int fn = 0; fn < 4; ++fn) {
            int r = row0 + wm + fm * 16 + g;
            int c = wn + fn * 8 + (q << 1);
            float b0v = bias[c], b1v = bias[c + 1];
            float v0 = acc[fm][fn][0] + b0v;
            float v1 = acc[fm][fn][1] + b1v;
            float v2 = acc[fm][fn][2] + b0v;
            float v3 = acc[fm][fn][3] + b1v;
            if (r < M)
                *(__nv_bfloat162*)(C16 + (size_t)r * BN + c) =
                    __float22bfloat162_rn(make_float2(v0, v1));
            if (r + 8 < M)
                *(__nv_bfloat162*)(C16 + (size_t)(r + 8) * BN + c) =
                    __float22bfloat162_rn(make_float2(v2, v3));
        }
    }
}

// ---------------- BF16 GEMM (K=128 per source), dual-problem batched ----------------
// fold: 0=store bf16 C16, 1=dot with g_vfeat into out, 2=dot with g_vdist into out
#define SAH 40

__device__ __forceinline__ void bf16_load_tile(
    __nv_bfloat16* As, __nv_bfloat16* Bs,
    const __nv_bfloat16* __restrict__ A, const __nv_bfloat16* __restrict__ Wt,
    int k0, int row0, int M, int tid)
{
#pragma unroll
    for (int i = 0; i < 2; ++i) {
        int c = tid + i * 256;
        int r = c >> 2;
        int j = c & 3;
        int gr = row0 + r;
        cp_async16(smem_u32p(As + r * SAH + j * 8),
                   A + (size_t)gr * HD + k0 + j * 8, gr < M);
    }
#pragma unroll
    for (int i = 0; i < 2; ++i) {
        int c = tid + i * 256;
        int r = c >> 2;
        int j = c & 3;
        cp_async16(smem_u32p(Bs + r * SAH + j * 8),
                   Wt + (size_t)r * HD + k0 + j * 8, 1);
    }
    asm volatile("cp.async.commit_group;\n" ::);
}

__global__ void __launch_bounds__(256, 2) bf16_gemm_dual(
    const __nv_bfloat16* __restrict__ A1a, const __nv_bfloat16* __restrict__ Wt1a,
    const __nv_bfloat16* __restrict__ A2a, const __nv_bfloat16* __restrict__ Wt2a,
    const float* __restrict__ biasa, __nv_bfloat16* __restrict__ C16a, int foldA,
    const __nv_bfloat16* __restrict__ A1b, const __nv_bfloat16* __restrict__ Wt1b,
    const float* __restrict__ biasb, __nv_bfloat16* __restrict__ C16b, int foldB,
    float* __restrict__ out, int M, int grid1)
{
    __shared__ __nv_bfloat16 smA[2][128 * SAH];
    __shared__ __nv_bfloat16 smB[2][128 * SAH];
    __shared__ float sfv[BM];
    __shared__ float sred[BM];

    int tid = threadIdx.x;
    int lane = tid & 31;
    int warp = tid >> 5;
    int wm = (warp >> 2) * 64;
    int wn = (warp & 3) * 32;
    int g = lane >> 2;
    int q = lane & 3;

    int probB = (blockIdx.x >= grid1);
    int row0 = (probB ? (blockIdx.x - grid1) : blockIdx.x) * BM;

    const __nv_bfloat16* Asrc[2];
    const __nv_bfloat16* Wsrc[2];
    int nsrc;
    const float* bias;
    __nv_bfloat16* C16;
    int fold;
    if (probB) {
        Asrc[0] = A1b; Wsrc[0] = Wt1b; Asrc[1] = A1b; Wsrc[1] = Wt1b;
        nsrc = 1; bias = biasb; C16 = C16b; fold = foldB;
    } else {
        Asrc[0] = A1a; Wsrc[0] = Wt1a; Asrc[1] = A2a; Wsrc[1] = Wt2a;
        nsrc = A2a ? 2 : 1; bias = biasa; C16 = C16a; fold = foldA;
    }

    if (fold && tid < BM) {
        sfv[tid] = (fold == 1) ? g_vfeat[tid] : g_vdist[tid];
        sred[tid] = 0.f;
    }

    float acc[4][4][4];
#pragma unroll
    for (int i = 0; i < 4; ++i)
#pragma unroll
        for (int j = 0; j < 4; ++j)
#pragma unroll
            for (int k = 0; k < 4; ++k) acc[i][j][k] = 0.f;

    int total = nsrc * 4;
    bf16_load_tile(smA[0], smB[0], Asrc[0], Wsrc[0], 0, row0, M, tid);

    for (int t = 0; t < total; ++t) {
        if (t + 1 < total) {
            int p = (t + 1) >> 2;
            int k0 = ((t + 1) & 3) * BK;
            bf16_load_tile(smA[(t + 1) & 1], smB[(t + 1) & 1],
                           Asrc[p], Wsrc[p], k0, row0, M, tid);
            asm volatile("cp.async.wait_group 1;\n" ::);
        } else {
            asm volatile("cp.async.wait_group 0;\n" ::);
        }
        __syncthreads();

        const __nv_bfloat16* As = smA[t & 1];
        const __nv_bfloat16* Bs = smB[t & 1];
#pragma unroll
        for (int kk = 0; kk < BK; kk += 16) {
            int kq = kk + 2 * q;
            unsigned a[4][4], b[4][2];
#pragma unroll
            for (int fm = 0; fm < 4; ++fm) {
                int m = wm + fm * 16 + g;
                a[fm][0] = *(const unsigned*)&As[m * SAH + kq];
                a[fm][1] = *(const unsigned*)&As[(m + 8) * SAH + kq];
                a[fm][2] = *(const unsigned*)&As[m * SAH + kq + 8];
                a[fm][3] = *(const unsigned*)&As[(m + 8) * SAH + kq + 8];
            }
#pragma unroll
            for (int fn = 0; fn < 4; ++fn) {
                int n = wn + fn * 8 + g;
                b[fn][0] = *(const unsigned*)&Bs[n * SAH + kq];
                b[fn][1] = *(const unsigned*)&Bs[n * SAH + kq + 8];
            }
#pragma unroll
            for (int fm = 0; fm < 4; ++fm)
#pragma unroll
                for (int fn = 0; fn < 4; ++fn)
                    mma_bf16(acc[fm][fn], a[fm], b[fn]);
        }
        __syncthreads();
    }

    if (fold) {
#pragma unroll
        for (int fm = 0; fm < 4; ++fm) {
            float p0 = 0.f, p8 = 0.f;
#pragma unroll
            for (int fn = 0; fn < 4; ++fn) {
                int c = wn + fn * 8 + (q << 1);
                float b0 = bias[c], b1 = bias[c + 1];
                float w0 = sfv[c], w1 = sfv[c + 1];
                p0 += fmaxf(acc[fm][fn][0] + b0, 0.f) * w0
                    + fmaxf(acc[fm][fn][1] + b1, 0.f) * w1;
                p8 += fmaxf(acc[fm][fn][2] + b0, 0.f) * w0
                    + fmaxf(acc[fm][fn][3] + b1, 0.f) * w1;
            }
            atomicAdd(&sred[wm + fm * 16 + g], p0);
            atomicAdd(&sred[wm + fm * 16 + g + 8], p8);
        }
        __syncthreads();
        if (tid < BM) {
            int r = row0 + tid;
            if (r < M) atomicAdd(out + r, sred[tid]);
        }
    } else {
#pragma unroll
        for (int fm = 0; fm < 4; ++fm) {
#pragma unroll
            for (int fn = 0; fn < 4; ++fn) {
                int r = row0 + wm + fm * 16 + g;
                int c = wn + fn * 8 + (q << 1);
                float b0 = bias[c], b1 = bias[c + 1];
                float v0 = fmaxf(acc[fm][fn][0] + b0, 0.f);
                float v1 = fmaxf(acc[fm][fn][1] + b1, 0.f);
                float v2 = fmaxf(acc[fm][fn][2] + b0, 0.f);
                float v3 = fmaxf(acc[fm][fn][3] + b1, 0.f);
                if (r < M)
                    *(__nv_bfloat162*)(C16 + (size_t)r * BN + c) =
                        __float22bfloat162_rn(make_float2(v0, v1));
                if (r + 8 < M)
                    *(__nv_bfloat162*)(C16 + (size_t)(r + 8) * BN + c) =
                        __float22bfloat162_rn(make_float2(v2, v3));
            }
        }
    }
}

// ---------------- sigmoid epilogue ----------------
__global__ void sigmoid_kernel(float* __restrict__ out, int M) {
    int i = blockIdx.x * blockDim.x + threadIdx.x;
    if (i >= M) return;
    float v = out[i] + g_cc;
    out[i] = 1.0f / (1.0f + __expf(-v));
}

// ---------------- launch ----------------
extern "C" void kernel_launch(void* const* d_in, const int* in_sizes, int n_in,
                              void* d_out, int out_size)
{
    const float* x          = (const float*)d_in[0];
    const void*  edge_index = d_in[1];
    const float* edge_attr  = (const float*)d_in[2];
    const float* pre_W      = (const float*)d_in[3];
    const float* pre_b      = (const float*)d_in[4];
    const float* c1_Ws      = (const float*)d_in[5];
    const float* c1_Wn      = (const float*)d_in[6];
    const float* c1_b       = (const float*)d_in[7];
    const float* c2_Ws      = (const float*)d_in[8];
    const float* c2_Wn      = (const float*)d_in[9];
    const float* c2_b       = (const float*)d_in[10];
    const float* np_W       = (const float*)d_in[11];
    const float* np_b       = (const float*)d_in[12];
    const float* d_W0       = (const float*)d_in[13];
    const float* d_b0       = (const float*)d_in[14];
    const float* d_W1       = (const float*)d_in[15];
    const float* d_b1       = (const float*)d_in[16];
    const float* d_W2       = (const float*)d_in[17];
    const float* d_b2       = (const float*)d_in[18];
    const float* d_W3       = (const float*)d_in[19];
    const float* d_b3       = (const float*)d_in[20];
    const float* final_W    = (const float*)d_in[21];
    const float* final_b    = (const float*)d_in[22];
    float* out = (float*)d_out;

    int M = NN;
    int E = in_sizes[1] / 2;
    if (E > EE) E = EE;

    __nv_bfloat16 *hb16, *h2b16, *aggb16, *y0b16, *y1b16, *wt;
    cudaGetSymbolAddress((void**)&hb16,   g_hb16);
    cudaGetSymbolAddress((void**)&h2b16,  g_h2b16);
    cudaGetSymbolAddress((void**)&aggb16, g_aggb16);
    cudaGetSymbolAddress((void**)&y0b16,  g_y0b16);
    cudaGetSymbolAddress((void**)&y1b16,  g_y1b16);
    cudaGetSymbolAddress((void**)&wt,     g_wt);

    cudaFuncSetAttribute(pre_gemm_kernel,
                         cudaFuncAttributeMaxDynamicSharedMemorySize, PRE_SMEM);

    int SG = (E + 255) / 256;                               // scatter blocks
    int PG = 1 + (6 * HD * HD + HD * FIN + 255) / 256;      // prep blocks
    int nb = (M + 1023) / 1024;                             // scan1 blocks

    // 1. histogram (+ zero out, block-local detect; counts pre-zeroed invariant)
    histogram_kernel<<<SG, 256>>>((const int*)edge_index, out, E, M);
    // 2. per-1024 inclusive scan
    scan1_kernel<<<nb, 1024>>>(M);
    // 3. offsets (+ in-block bsum reduce, restore counts=0)
    scan3_kernel<<<(M + 255) / 256, 256>>>(M, E, nb);
    // 4. scatter + constant prep (independent halves, one launch)
    scatter_prep_kernel<<<SG + PG, 256>>>(
        (const int*)edge_index, E, SG,
        np_W, np_b, d_W3, d_b3, final_W, final_b,
        c1_Ws, c1_Wn, c2_Ws, c2_Wn, d_W1, d_W2, pre_W);

    const __nv_bfloat16* wt_c1s = wt + 0 * HD * HD;
    const __nv_bfloat16* wt_c1n = wt + 1 * HD * HD;
    const __nv_bfloat16* wt_c2s = wt + 2 * HD * HD;
    const __nv_bfloat16* wt_c2n = wt + 3 * HD * HD;
    const __nv_bfloat16* wt_d1  = wt + 4 * HD * HD;
    const __nv_bfloat16* wt_d2  = wt + 5 * HD * HD;
    const __nv_bfloat16* wt_pre = wt + 6 * HD * HD;

    int G  = (M + BM - 1) / BM;
    int DG = (M + D0_ROWS - 1) / D0_ROWS;

    // 5. pre layer (bf16 MMA) + dist0, one launch
    pre_gemm_kernel<<<G + DG, 256, PRE_SMEM>>>(
        x, wt_pre, pre_b, hb16, M, G, edge_attr, d_W0, d_b0, y0b16);
    // 6. agg1
    mean_agg_kernel<<<(M * 16 + 255) / 256, 256>>>(hb16, aggb16, M);
    // 7. layer1 conv (c1) + dist layer1 (d1)
    bf16_gemm_dual<<<2 * G, 256>>>(
        hb16, wt_c1s, aggb16, wt_c1n, c1_b, h2b16, 0,
        y0b16, wt_d1, d_b1, y1b16, 0,
        nullptr, M, G);
    // 8. agg2
    mean_agg_kernel<<<(M * 16 + 255) / 256, 256>>>(h2b16, aggb16, M);
    // 9. layer2 conv (c2) + dist layer2 (d2), fused final dot
    bf16_gemm_dual<<<2 * G, 256>>>(
        h2b16, wt_c2s, aggb16, wt_c2n, c2_b, nullptr, 1,
        y1b16, wt_d2, d_b2, nullptr, 2,
        out, M, G);
    // 10. sigmoid
    sigmoid_kernel<<<(M + 255) / 256, 256>>>(out, M);
}